// round 1
// baseline (speedup 1.0000x reference)
#include <cuda_runtime.h>
#include <cuda_bf16.h>
#include <math.h>

// ---------------------------------------------------------------------------
// SORNet: s_{k+1} = (s_k @ T + yMF) @ invM  ==  s_k @ G + c
//   G = T @ invM, c = yMF @ invM, invM = inv(w*D + L), T = (w-1)*D - U
// Outputs: [s_final (BS*N) | traj (itr+1, BS, N)] with traj[0]=0, traj[k]=s_k.
// ---------------------------------------------------------------------------

#define MAXN 1024
#define MAXBS 2048

__device__ __align__(16) float g_invM[MAXN * MAXN];
__device__ __align__(16) float g_T[MAXN * MAXN];
__device__ __align__(16) float g_G[MAXN * MAXN];
__device__ __align__(16) float g_yMF[MAXBS * MAXN];
__device__ __align__(16) float g_c[MAXBS * MAXN];
__device__ __align__(16) float g_s0[MAXBS * MAXN];
__device__ __align__(16) float g_d[MAXN];

// ---- packed f32x2 helpers (Blackwell; ptxas never auto-fuses these) -------
__device__ __forceinline__ unsigned long long pack2(float x) {
    unsigned long long r;
    unsigned u = __float_as_uint(x);
    asm("mov.b64 %0, {%1, %1};" : "=l"(r) : "r"(u));
    return r;
}
__device__ __forceinline__ unsigned long long ffma2(unsigned long long a,
                                                    unsigned long long b,
                                                    unsigned long long c) {
    unsigned long long d;
    asm("fma.rn.f32x2 %0, %1, %2, %3;" : "=l"(d) : "l"(a), "l"(b), "l"(c));
    return d;
}
__device__ __forceinline__ float2 unpack2(unsigned long long v) {
    unsigned lo, hi;
    asm("mov.b64 {%0, %1}, %2;" : "=r"(lo), "=r"(hi) : "l"(v));
    return make_float2(__uint_as_float(lo), __uint_as_float(hi));
}

// ---------------------------------------------------------------------------
// prep: d = diag(A); T = (w-1)*D - U
// ---------------------------------------------------------------------------
__global__ void prep_kernel(const float* __restrict__ A,
                            const float* __restrict__ pw,
                            float* __restrict__ T, float* __restrict__ dvec,
                            int n) {
    int idx = blockIdx.x * blockDim.x + threadIdx.x;
    if (idx >= n * n) return;
    int i = idx / n;
    int k = idx - i * n;
    float w = *pw;
    float a = A[idx];
    float t = 0.0f;
    if (i == k) {
        t = (w - 1.0f) * a;
        dvec[i] = a;
    } else if (i < k) {
        t = -a;
    }
    T[idx] = t;
}

// ---------------------------------------------------------------------------
// trinv: invM = inv(w*D + L).  One warp per column, forward substitution.
// M_ij = A_ij (i>j), M_ii = w*A_ii.  Column j of X: x_j = 1/M_jj,
// x_i = -(sum_{k=j..i-1} A_ik x_k) / M_ii.  Upper part zeroed.
// ---------------------------------------------------------------------------
__global__ __launch_bounds__(256) void trinv_kernel(const float* __restrict__ A,
                                                    const float* __restrict__ pw,
                                                    float* __restrict__ X, int n) {
    __shared__ float xs_all[8][MAXN];
    int lane = threadIdx.x & 31;
    int warpInBlk = threadIdx.x >> 5;
    int j = blockIdx.x * 8 + warpInBlk;
    if (j >= n) return;
    float* xs = xs_all[warpInBlk];
    float w = *pw;

    // zero upper part of this column
    for (int i = lane; i < j; i += 32) X[(size_t)i * n + j] = 0.0f;

    float xjj = 1.0f / (w * A[(size_t)j * n + j]);
    if (lane == 0) {
        xs[j] = xjj;
        X[(size_t)j * n + j] = xjj;
    }
    __syncwarp();
    for (int i = j + 1; i < n; i++) {
        const float* Arow = A + (size_t)i * n;
        float s = 0.0f;
        for (int k = j + lane; k < i; k += 32) s += Arow[k] * xs[k];
#pragma unroll
        for (int o = 16; o > 0; o >>= 1) s += __shfl_xor_sync(0xFFFFFFFFu, s, o);
        float xi = -s / (w * Arow[i]);
        if (lane == 0) {
            xs[i] = xi;
            X[(size_t)i * n + j] = xi;
        }
        __syncwarp();
    }
}

// ---------------------------------------------------------------------------
// s0 = yMF / d  (broadcast divide); also zero traj[0]
// ---------------------------------------------------------------------------
__global__ void s0_kernel(const float* __restrict__ yMF,
                          const float* __restrict__ dvec,
                          float* __restrict__ s0, float* __restrict__ traj0,
                          int total, int n) {
    int i = blockIdx.x * blockDim.x + threadIdx.x;
    if (i < total) {
        s0[i] = yMF[i] / dvec[i & (n - 1)];
        traj0[i] = 0.0f;
    }
}

// ---------------------------------------------------------------------------
// GEMM: D = A[M,K] @ B(+opt transpose)[K,N] (+ Cadd), optional dup store D2.
// 128x128x16 tile, 256 threads, 8x8 per thread, packed f32x2 FMA inner loop.
// Assumes M%128==0, N%128==0, K%16==0.
// ---------------------------------------------------------------------------
#define BM 128
#define BN 128
#define BK 16

template <bool TRANSB, bool ADDC>
__global__ __launch_bounds__(256) void gemm_kernel(
    const float* __restrict__ A, const float* __restrict__ B,
    const float* __restrict__ Cadd, float* __restrict__ D,
    float* __restrict__ D2, int M, int Nn, int K) {
    __shared__ __align__(16) float As[BK][BM];
    __shared__ __align__(16) float Bs[BK][BN];

    int tid = threadIdx.x;
    int tx = tid & 15;
    int ty = tid >> 4;
    int bn0 = blockIdx.x * BN;
    int bm0 = blockIdx.y * BM;

    unsigned long long acc[8][4];
#pragma unroll
    for (int r = 0; r < 8; r++)
#pragma unroll
        for (int c = 0; c < 4; c++) acc[r][c] = 0ull;

    for (int k0 = 0; k0 < K; k0 += BK) {
        // A tile: 128 rows x 16 k, transposed into As[k][m]
#pragma unroll
        for (int i = 0; i < 2; i++) {
            int v = tid + i * 256;
            int row = v >> 2;
            int kc = (v & 3) << 2;
            float4 t = *reinterpret_cast<const float4*>(
                &A[(size_t)(bm0 + row) * K + k0 + kc]);
            As[kc + 0][row] = t.x;
            As[kc + 1][row] = t.y;
            As[kc + 2][row] = t.z;
            As[kc + 3][row] = t.w;
        }
        if (!TRANSB) {
#pragma unroll
            for (int i = 0; i < 2; i++) {
                int v = tid + i * 256;
                int r = v >> 5;
                int c = (v & 31) << 2;
                *reinterpret_cast<float4*>(&Bs[r][c]) =
                    *reinterpret_cast<const float4*>(
                        &B[(size_t)(k0 + r) * Nn + bn0 + c]);
            }
        } else {
            // B given as [Nn, K] row-major (C = A @ B^T)
#pragma unroll
            for (int i = 0; i < 2; i++) {
                int v = tid + i * 256;
                int nr = v >> 2;
                int kc = (v & 3) << 2;
                float4 t = *reinterpret_cast<const float4*>(
                    &B[(size_t)(bn0 + nr) * K + k0 + kc]);
                Bs[kc + 0][nr] = t.x;
                Bs[kc + 1][nr] = t.y;
                Bs[kc + 2][nr] = t.z;
                Bs[kc + 3][nr] = t.w;
            }
        }
        __syncthreads();
#pragma unroll
        for (int k = 0; k < BK; k++) {
            float4 a0 = *reinterpret_cast<const float4*>(&As[k][ty * 8]);
            float4 a1 = *reinterpret_cast<const float4*>(&As[k][ty * 8 + 4]);
            ulonglong2 bA =
                *reinterpret_cast<const ulonglong2*>(&Bs[k][tx * 8]);
            ulonglong2 bB =
                *reinterpret_cast<const ulonglong2*>(&Bs[k][tx * 8 + 4]);
            unsigned long long bp0 = bA.x, bp1 = bA.y, bp2 = bB.x, bp3 = bB.y;
            float av[8] = {a0.x, a0.y, a0.z, a0.w, a1.x, a1.y, a1.z, a1.w};
#pragma unroll
            for (int r = 0; r < 8; r++) {
                unsigned long long ap = pack2(av[r]);
                acc[r][0] = ffma2(ap, bp0, acc[r][0]);
                acc[r][1] = ffma2(ap, bp1, acc[r][1]);
                acc[r][2] = ffma2(ap, bp2, acc[r][2]);
                acc[r][3] = ffma2(ap, bp3, acc[r][3]);
            }
        }
        __syncthreads();
    }

    // epilogue
#pragma unroll
    for (int r = 0; r < 8; r++) {
        size_t row = (size_t)(bm0 + ty * 8 + r);
        int col = bn0 + tx * 8;
        float2 p0 = unpack2(acc[r][0]);
        float2 p1 = unpack2(acc[r][1]);
        float2 p2 = unpack2(acc[r][2]);
        float2 p3 = unpack2(acc[r][3]);
        float4 o0 = make_float4(p0.x, p0.y, p1.x, p1.y);
        float4 o1 = make_float4(p2.x, p2.y, p3.x, p3.y);
        if (ADDC) {
            float4 c0 = *reinterpret_cast<const float4*>(&Cadd[row * Nn + col]);
            float4 c1 =
                *reinterpret_cast<const float4*>(&Cadd[row * Nn + col + 4]);
            o0.x += c0.x; o0.y += c0.y; o0.z += c0.z; o0.w += c0.w;
            o1.x += c1.x; o1.y += c1.y; o1.z += c1.z; o1.w += c1.w;
        }
        *reinterpret_cast<float4*>(&D[row * Nn + col]) = o0;
        *reinterpret_cast<float4*>(&D[row * Nn + col + 4]) = o1;
        if (D2 != nullptr) {
            *reinterpret_cast<float4*>(&D2[row * Nn + col]) = o0;
            *reinterpret_cast<float4*>(&D2[row * Nn + col + 4]) = o1;
        }
    }
}

// ---------------------------------------------------------------------------
extern "C" void kernel_launch(void* const* d_in, const int* in_sizes, int n_in,
                              void* d_out, int out_size) {
    const float* A = (const float*)d_in[0];
    const float* H = (const float*)d_in[1];
    const float* y = (const float*)d_in[2];
    const float* pw = (const float*)d_in[3];  // inv_omega (device scalar)

    int n = (int)(sqrt((double)in_sizes[0]) + 0.5);
    int bs = in_sizes[2] / n;
    int itr = out_size / (bs * n) - 2;  // out = s_final + (itr+1) traj slabs

    float *invM, *T, *G, *yMF, *c, *s0;
    cudaGetSymbolAddress((void**)&invM, g_invM);
    cudaGetSymbolAddress((void**)&T, g_T);
    cudaGetSymbolAddress((void**)&G, g_G);
    cudaGetSymbolAddress((void**)&yMF, g_yMF);
    cudaGetSymbolAddress((void**)&c, g_c);
    cudaGetSymbolAddress((void**)&s0, g_s0);
    float* dvec;
    cudaGetSymbolAddress((void**)&dvec, g_d);

    float* out = (float*)d_out;
    float* traj = out + (size_t)bs * n;  // traj[k] at traj + k*bs*n

    // 1) T, diag
    prep_kernel<<<(n * n + 255) / 256, 256>>>(A, pw, T, dvec, n);
    // 2) invM (warp per column)
    trinv_kernel<<<(n + 7) / 8, 256>>>(A, pw, invM, n);
    // 3) yMF = y @ H^T
    {
        dim3 grid(n / BN, bs / BM);
        gemm_kernel<true, false><<<grid, 256>>>(y, H, nullptr, yMF, nullptr,
                                                bs, n, n);
    }
    // 4) s0 = yMF / d ; traj[0] = 0
    s0_kernel<<<(bs * n + 255) / 256, 256>>>(yMF, dvec, s0, traj, bs * n, n);
    // 5) c = yMF @ invM
    {
        dim3 grid(n / BN, bs / BM);
        gemm_kernel<false, false><<<grid, 256>>>(yMF, invM, nullptr, c,
                                                 nullptr, bs, n, n);
    }
    // 6) G = T @ invM
    {
        dim3 grid(n / BN, n / BM);
        gemm_kernel<false, false><<<grid, 256>>>(T, invM, nullptr, G, nullptr,
                                                 n, n, n);
    }
    // 7) iterate: s_k = s_{k-1} @ G + c   (write into traj slab k)
    dim3 grid(n / BN, bs / BM);
    for (int k = 1; k <= itr; k++) {
        const float* src = (k == 1) ? s0 : (traj + (size_t)(k - 1) * bs * n);
        float* dst = traj + (size_t)k * bs * n;
        float* dup = (k == itr) ? out : nullptr;  // s_final
        gemm_kernel<false, true><<<grid, 256>>>(src, G, c, dst, dup, bs, n, n);
    }
}

// round 4
// speedup vs baseline: 1.8568x; 1.8568x over previous
#include <cuda_runtime.h>
#include <cuda_bf16.h>
#include <stdint.h>

// ---------------------------------------------------------------------------
// SORNet via affine recurrence  s_k = s_{k-1} @ G + c, GEMMs on legacy tensor
// cores (mma.sync m16n8k16 bf16 -> f32) with bf16x3 split operands.
//   invM = inv(w*D + L)   (fp32 forward substitution, one warp/column)
//   T    = (w-1)*D - U
//   yMF  = y @ H^T            (B array = H [n][k])
//   c    = yMF @ invM         (B array = invM^T [n][k])
//   G^T  = invM^T @ T^T       (B array = T [n][k]; epilogue emits GT splits)
//   loop: s_k = s_{k-1} @ G + c  (B array = G^T splits; emits next splits)
// Output: [s_final | traj(itr+1 slabs)], traj[0]=0.
// NOTE: tcgen05 unavailable (harness compiles PTX for plain sm_103).
// ---------------------------------------------------------------------------

#define ND 1024
#define BSD 2048

// fp32 scratch
__device__ __align__(1024) float g_invM[ND * ND];
__device__ __align__(1024) float g_yMF[BSD * ND];
__device__ __align__(1024) float g_c[BSD * ND];
__device__ __align__(1024) float g_G[ND * ND];
__device__ float g_d[ND];

// bf16 split operands
__device__ __align__(1024) __nv_bfloat16 g_Hhi[ND * ND];
__device__ __align__(1024) __nv_bfloat16 g_Hlo[ND * ND];
__device__ __align__(1024) __nv_bfloat16 g_yhi[BSD * ND];
__device__ __align__(1024) __nv_bfloat16 g_ylo[BSD * ND];
__device__ __align__(1024) __nv_bfloat16 g_yMFhi[BSD * ND];
__device__ __align__(1024) __nv_bfloat16 g_yMFlo[BSD * ND];
__device__ __align__(1024) __nv_bfloat16 g_iMThi[ND * ND];
__device__ __align__(1024) __nv_bfloat16 g_iMTlo[ND * ND];
__device__ __align__(1024) __nv_bfloat16 g_Thi[ND * ND];
__device__ __align__(1024) __nv_bfloat16 g_Tlo[ND * ND];
__device__ __align__(1024) __nv_bfloat16 g_GThi[ND * ND];
__device__ __align__(1024) __nv_bfloat16 g_GTlo[ND * ND];
__device__ __align__(1024) __nv_bfloat16 g_sAhi[BSD * ND];
__device__ __align__(1024) __nv_bfloat16 g_sAlo[BSD * ND];
__device__ __align__(1024) __nv_bfloat16 g_sBhi[BSD * ND];
__device__ __align__(1024) __nv_bfloat16 g_sBlo[BSD * ND];

// ---------------------------------------------------------------------------
__device__ __forceinline__ uint32_t smem_u32(const void* p) {
    uint32_t a;
    asm("{ .reg .u64 t; cvta.to.shared.u64 t, %1; cvt.u32.u64 %0, t; }"
        : "=r"(a) : "l"(p));
    return a;
}

__device__ __forceinline__ void ldm_x4(uint32_t (&r)[4], uint32_t addr) {
    asm volatile(
        "ldmatrix.sync.aligned.m8n8.x4.shared.b16 {%0,%1,%2,%3}, [%4];"
        : "=r"(r[0]), "=r"(r[1]), "=r"(r[2]), "=r"(r[3]) : "r"(addr));
}

__device__ __forceinline__ void mma16816(float* c, const uint32_t* a,
                                         const uint32_t* b) {
    asm volatile(
        "mma.sync.aligned.m16n8k16.row.col.f32.bf16.bf16.f32 "
        "{%0,%1,%2,%3}, {%4,%5,%6,%7}, {%8,%9}, {%0,%1,%2,%3};"
        : "+f"(c[0]), "+f"(c[1]), "+f"(c[2]), "+f"(c[3])
        : "r"(a[0]), "r"(a[1]), "r"(a[2]), "r"(a[3]), "r"(b[0]), "r"(b[1]));
}

__device__ __forceinline__ void cp16(uint32_t sdst, const void* gsrc) {
    asm volatile("cp.async.cg.shared.global [%0], [%1], 16;" ::"r"(sdst),
                 "l"(gsrc));
}
#define CP_COMMIT() asm volatile("cp.async.commit_group;" ::: "memory")
#define CP_WAIT2() asm volatile("cp.async.wait_group 2;" ::: "memory")

__device__ __forceinline__ void split2(float x, __nv_bfloat16& h,
                                       __nv_bfloat16& l) {
    h = __float2bfloat16(x);
    l = __float2bfloat16(x - __bfloat162float(h));
}

// ---------------------------------------------------------------------------
// small kernels
// ---------------------------------------------------------------------------
__global__ void prep_split_kernel(const float* __restrict__ A,
                                  const float* __restrict__ pw,
                                  __nv_bfloat16* __restrict__ Thi,
                                  __nv_bfloat16* __restrict__ Tlo,
                                  float* __restrict__ dvec) {
    int idx = blockIdx.x * blockDim.x + threadIdx.x;
    if (idx >= ND * ND) return;
    int i = idx >> 10, k = idx & (ND - 1);
    float w = *pw;
    float a = A[idx];
    float t = 0.0f;
    if (i == k) {
        t = (w - 1.0f) * a;
        dvec[i] = a;
    } else if (i < k) {
        t = -a;
    }
    __nv_bfloat16 h, l;
    split2(t, h, l);
    Thi[idx] = h;
    Tlo[idx] = l;
}

__global__ void split_ew_kernel(const float* __restrict__ in,
                                __nv_bfloat16* __restrict__ hi,
                                __nv_bfloat16* __restrict__ lo, int total) {
    int i = blockIdx.x * blockDim.x + threadIdx.x;
    if (i >= total) return;
    __nv_bfloat16 h, l;
    split2(in[i], h, l);
    hi[i] = h;
    lo[i] = l;
}

__global__ void tsplit_kernel(const float* __restrict__ in,
                              __nv_bfloat16* __restrict__ oh,
                              __nv_bfloat16* __restrict__ ol) {
    __shared__ float t[32][33];
    int bx = blockIdx.x * 32, by = blockIdx.y * 32;
    for (int r = threadIdx.y; r < 32; r += 8)
        t[r][threadIdx.x] = in[(size_t)(by + r) * ND + bx + threadIdx.x];
    __syncthreads();
    for (int r = threadIdx.y; r < 32; r += 8) {
        float v = t[threadIdx.x][r];
        __nv_bfloat16 h, l;
        split2(v, h, l);
        size_t o = (size_t)(bx + r) * ND + by + threadIdx.x;
        oh[o] = h;
        ol[o] = l;
    }
}

__global__ void s0split_kernel(const float* __restrict__ yMF,
                               const float* __restrict__ dvec,
                               __nv_bfloat16* __restrict__ hi,
                               __nv_bfloat16* __restrict__ lo,
                               float* __restrict__ traj0, int total) {
    int i = blockIdx.x * blockDim.x + threadIdx.x;
    if (i >= total) return;
    float v = yMF[i] / dvec[i & (ND - 1)];
    __nv_bfloat16 h, l;
    split2(v, h, l);
    hi[i] = h;
    lo[i] = l;
    traj0[i] = 0.0f;
}

__global__ __launch_bounds__(256) void trinv_kernel(const float* __restrict__ A,
                                                    const float* __restrict__ pw,
                                                    float* __restrict__ X) {
    __shared__ float xs_all[8][ND];
    int lane = threadIdx.x & 31;
    int warpInBlk = threadIdx.x >> 5;
    int j = blockIdx.x * 8 + warpInBlk;
    if (j >= ND) return;
    float* xs = xs_all[warpInBlk];
    float w = *pw;
    for (int i = lane; i < j; i += 32) X[(size_t)i * ND + j] = 0.0f;
    float xjj = 1.0f / (w * A[(size_t)j * ND + j]);
    if (lane == 0) {
        xs[j] = xjj;
        X[(size_t)j * ND + j] = xjj;
    }
    __syncwarp();
    for (int i = j + 1; i < ND; i++) {
        const float* Arow = A + (size_t)i * ND;
        float s = 0.0f;
        for (int k = j + lane; k < i; k += 32) s += Arow[k] * xs[k];
#pragma unroll
        for (int o = 16; o > 0; o >>= 1) s += __shfl_xor_sync(0xFFFFFFFFu, s, o);
        float xi = -s / (w * Arow[i]);
        if (lane == 0) {
            xs[i] = xi;
            X[(size_t)i * ND + j] = xi;
        }
        __syncwarp();
    }
}

// ---------------------------------------------------------------------------
// split-GEMM on mma.sync: D[M,1024] = Ahi@Bhi^T + Ahi@Blo^T + Alo@Bhi^T (+C)
// A arrays: [M][1024] bf16 row-major; B arrays: [1024][1024] bf16, B^T layout
// (B[n][k]).  CTA 128x128, BK=32, 3-stage cp.async pipeline, 8 warps (2x4),
// warp tile 64x32.  Epilogue: +Cadd, fp32 out (+dup), optional bf16 splits.
// ---------------------------------------------------------------------------
#define RS 40               // padded row stride in bf16 (80 B)
#define TILE_E (128 * RS)   // 5120 bf16 per tile (10240 B)
#define STG_E (4 * TILE_E)  // Ahi, Alo, Bhi, Blo
#define NSTAGE 3
#define GEMM_SMEM (NSTAGE * STG_E * 2)
#define NKCH 32  // 1024 / 32

__global__ __launch_bounds__(256, 1) void mma_gemm(
    const __nv_bfloat16* __restrict__ Ahi, const __nv_bfloat16* __restrict__ Alo,
    const __nv_bfloat16* __restrict__ Bhi, const __nv_bfloat16* __restrict__ Blo,
    const float* __restrict__ Cadd, float* __restrict__ outD,
    float* __restrict__ outDup, __nv_bfloat16* __restrict__ nHi,
    __nv_bfloat16* __restrict__ nLo) {
    extern __shared__ __align__(128) __nv_bfloat16 smg[];
    const uint32_t sbase = smem_u32(smg);
    const int tid = threadIdx.x;
    const int lane = tid & 31, wid = tid >> 5;
    const int warpM = wid >> 2, warpN = wid & 3;  // 2 x 4 warp grid
    const int bm0 = blockIdx.y * 128, bn0 = blockIdx.x * 128;

    float acc[4][4][4];
#pragma unroll
    for (int a = 0; a < 4; a++)
#pragma unroll
        for (int b = 0; b < 4; b++)
#pragma unroll
            for (int e = 0; e < 4; e++) acc[a][b][e] = 0.0f;

    // cp.async per-thread chunk coords (2 chunks per tile)
    const int c0r = tid >> 2;            // 0..63
    const int c0k = (tid & 3) * 8;       // bf16 elems
    const int c1r = c0r + 64;

    // ldmatrix per-lane offsets (element units within a tile)
    const int aRow = warpM * 64 + (lane & 15);
    const int aOffB = aRow * RS + ((lane >> 4) << 3);
    const int nB = warpN * 32 + ((lane >> 4) << 3) + (lane & 7);
    const int bOffB = nB * RS + (((lane >> 3) & 1) << 3);

#define LOAD_STAGE(slot, kc0)                                                   \
    do {                                                                        \
        uint32_t sa = sbase + (uint32_t)(slot) * (STG_E * 2);                   \
        int kk = (kc0);                                                         \
        cp16(sa + (uint32_t)(c0r * RS + c0k) * 2,                               \
             Ahi + (size_t)(bm0 + c0r) * ND + kk + c0k);                        \
        cp16(sa + (uint32_t)(c1r * RS + c0k) * 2,                               \
             Ahi + (size_t)(bm0 + c1r) * ND + kk + c0k);                        \
        cp16(sa + (uint32_t)(TILE_E + c0r * RS + c0k) * 2,                      \
             Alo + (size_t)(bm0 + c0r) * ND + kk + c0k);                        \
        cp16(sa + (uint32_t)(TILE_E + c1r * RS + c0k) * 2,                      \
             Alo + (size_t)(bm0 + c1r) * ND + kk + c0k);                        \
        cp16(sa + (uint32_t)(2 * TILE_E + c0r * RS + c0k) * 2,                  \
             Bhi + (size_t)(bn0 + c0r) * ND + kk + c0k);                        \
        cp16(sa + (uint32_t)(2 * TILE_E + c1r * RS + c0k) * 2,                  \
             Bhi + (size_t)(bn0 + c1r) * ND + kk + c0k);                        \
        cp16(sa + (uint32_t)(3 * TILE_E + c0r * RS + c0k) * 2,                  \
             Blo + (size_t)(bn0 + c0r) * ND + kk + c0k);                        \
        cp16(sa + (uint32_t)(3 * TILE_E + c1r * RS + c0k) * 2,                  \
             Blo + (size_t)(bn0 + c1r) * ND + kk + c0k);                        \
        CP_COMMIT();                                                            \
    } while (0)

    LOAD_STAGE(0, 0);
    LOAD_STAGE(1, 32);

    for (int ck = 0; ck < NKCH; ck++) {
        if (ck + 2 < NKCH) {
            int slot2 = (ck + 2) % NSTAGE;
            LOAD_STAGE(slot2, (ck + 2) * 32);
        } else {
            CP_COMMIT();
        }
        CP_WAIT2();
        __syncthreads();

        uint32_t sa = sbase + (uint32_t)(ck % NSTAGE) * (STG_E * 2);
#pragma unroll
        for (int ks = 0; ks < 2; ks++) {
            uint32_t ah[4][4], al[4][4];
            uint32_t bh[4][2], bl[4][2];
#pragma unroll
            for (int im = 0; im < 4; im++) {
                uint32_t off = (uint32_t)(aOffB + im * 16 * RS + ks * 16) * 2;
                ldm_x4(ah[im], sa + off);
                ldm_x4(al[im], sa + (uint32_t)(TILE_E * 2) + off);
            }
#pragma unroll
            for (int ig = 0; ig < 2; ig++) {
                uint32_t off = (uint32_t)(bOffB + ig * 16 * RS + ks * 16) * 2;
                uint32_t t[4];
                ldm_x4(t, sa + (uint32_t)(2 * TILE_E * 2) + off);
                bh[2 * ig][0] = t[0]; bh[2 * ig][1] = t[1];
                bh[2 * ig + 1][0] = t[2]; bh[2 * ig + 1][1] = t[3];
                ldm_x4(t, sa + (uint32_t)(3 * TILE_E * 2) + off);
                bl[2 * ig][0] = t[0]; bl[2 * ig][1] = t[1];
                bl[2 * ig + 1][0] = t[2]; bl[2 * ig + 1][1] = t[3];
            }
#pragma unroll
            for (int im = 0; im < 4; im++) {
#pragma unroll
                for (int in = 0; in < 4; in++) {
                    mma16816(acc[im][in], ah[im], bh[in]);
                    mma16816(acc[im][in], ah[im], bl[in]);
                    mma16816(acc[im][in], al[im], bh[in]);
                }
            }
        }
        __syncthreads();
    }

    // ---- epilogue ----
    const int gr = lane >> 2;
    const int gc = (lane & 3) * 2;
#pragma unroll
    for (int im = 0; im < 4; im++) {
#pragma unroll
        for (int in = 0; in < 4; in++) {
            int row0 = bm0 + warpM * 64 + im * 16 + gr;
            int col = bn0 + warpN * 32 + in * 8 + gc;
#pragma unroll
            for (int hh = 0; hh < 2; hh++) {
                size_t off = (size_t)(row0 + hh * 8) * ND + col;
                float x = acc[im][in][hh * 2 + 0];
                float y = acc[im][in][hh * 2 + 1];
                if (Cadd) {
                    float2 cv = *reinterpret_cast<const float2*>(Cadd + off);
                    x += cv.x;
                    y += cv.y;
                }
                *reinterpret_cast<float2*>(outD + off) = make_float2(x, y);
                if (outDup)
                    *reinterpret_cast<float2*>(outDup + off) = make_float2(x, y);
                if (nHi) {
                    __nv_bfloat16 hx, lx, hy, ly;
                    split2(x, hx, lx);
                    split2(y, hy, ly);
                    *reinterpret_cast<__nv_bfloat162*>(nHi + off) =
                        __halves2bfloat162(hx, hy);
                    *reinterpret_cast<__nv_bfloat162*>(nLo + off) =
                        __halves2bfloat162(lx, ly);
                }
            }
        }
    }
#undef LOAD_STAGE
}

// ---------------------------------------------------------------------------
extern "C" void kernel_launch(void* const* d_in, const int* in_sizes, int n_in,
                              void* d_out, int out_size) {
    const float* A = (const float*)d_in[0];
    const float* H = (const float*)d_in[1];
    const float* y = (const float*)d_in[2];
    const float* pw = (const float*)d_in[3];

    int n = ND;
    int bs = in_sizes[2] / n;
    int itr = out_size / (bs * n) - 2;

    float *invM, *yMF, *cbuf, *Gbuf, *dvec;
    cudaGetSymbolAddress((void**)&invM, g_invM);
    cudaGetSymbolAddress((void**)&yMF, g_yMF);
    cudaGetSymbolAddress((void**)&cbuf, g_c);
    cudaGetSymbolAddress((void**)&Gbuf, g_G);
    cudaGetSymbolAddress((void**)&dvec, g_d);
    __nv_bfloat16 *Hhi, *Hlo, *yhi, *ylo, *yMFhi, *yMFlo, *iMThi, *iMTlo;
    __nv_bfloat16 *Thi, *Tlo, *GThi, *GTlo, *sAhi, *sAlo, *sBhi, *sBlo;
    cudaGetSymbolAddress((void**)&Hhi, g_Hhi);
    cudaGetSymbolAddress((void**)&Hlo, g_Hlo);
    cudaGetSymbolAddress((void**)&yhi, g_yhi);
    cudaGetSymbolAddress((void**)&ylo, g_ylo);
    cudaGetSymbolAddress((void**)&yMFhi, g_yMFhi);
    cudaGetSymbolAddress((void**)&yMFlo, g_yMFlo);
    cudaGetSymbolAddress((void**)&iMThi, g_iMThi);
    cudaGetSymbolAddress((void**)&iMTlo, g_iMTlo);
    cudaGetSymbolAddress((void**)&Thi, g_Thi);
    cudaGetSymbolAddress((void**)&Tlo, g_Tlo);
    cudaGetSymbolAddress((void**)&GThi, g_GThi);
    cudaGetSymbolAddress((void**)&GTlo, g_GTlo);
    cudaGetSymbolAddress((void**)&sAhi, g_sAhi);
    cudaGetSymbolAddress((void**)&sAlo, g_sAlo);
    cudaGetSymbolAddress((void**)&sBhi, g_sBhi);
    cudaGetSymbolAddress((void**)&sBlo, g_sBlo);

    cudaFuncSetAttribute(mma_gemm, cudaFuncAttributeMaxDynamicSharedMemorySize,
                         GEMM_SMEM);

    float* out = (float*)d_out;
    float* traj = out + (size_t)bs * n;

    // setup
    prep_split_kernel<<<(n * n + 255) / 256, 256>>>(A, pw, Thi, Tlo, dvec);
    trinv_kernel<<<(n + 7) / 8, 256>>>(A, pw, invM);
    split_ew_kernel<<<(bs * n + 255) / 256, 256>>>(y, yhi, ylo, bs * n);
    split_ew_kernel<<<(n * n + 255) / 256, 256>>>(H, Hhi, Hlo, n * n);
    tsplit_kernel<<<dim3(32, 32), dim3(32, 8)>>>(invM, iMThi, iMTlo);

    dim3 gBig(n / 128, bs / 128);
    dim3 gSq(n / 128, n / 128);

    // yMF = y @ H^T  (emit yMF splits)
    mma_gemm<<<gBig, 256, GEMM_SMEM>>>(yhi, ylo, Hhi, Hlo, nullptr, yMF,
                                       nullptr, yMFhi, yMFlo);
    // s0 splits + traj[0] = 0
    s0split_kernel<<<(bs * n + 255) / 256, 256>>>(yMF, dvec, sAhi, sAlo, traj,
                                                  bs * n);
    // c = yMF @ invM
    mma_gemm<<<gBig, 256, GEMM_SMEM>>>(yMFhi, yMFlo, iMThi, iMTlo, nullptr,
                                       cbuf, nullptr, nullptr, nullptr);
    // G^T = invM^T @ T^T  (emit GT splits)
    mma_gemm<<<gSq, 256, GEMM_SMEM>>>(iMThi, iMTlo, Thi, Tlo, nullptr, Gbuf,
                                      nullptr, GThi, GTlo);

    // loop: s_k = s_{k-1} @ G + c
    for (int k = 1; k <= itr; k++) {
        float* dst = traj + (size_t)k * bs * n;
        float* dup = (k == itr) ? out : nullptr;
        bool aIsA = (k & 1);
        __nv_bfloat16* nh = (k == itr) ? nullptr : (aIsA ? sBhi : sAhi);
        __nv_bfloat16* nl = (k == itr) ? nullptr : (aIsA ? sBlo : sAlo);
        if (aIsA)
            mma_gemm<<<gBig, 256, GEMM_SMEM>>>(sAhi, sAlo, GThi, GTlo, cbuf,
                                               dst, dup, nh, nl);
        else
            mma_gemm<<<gBig, 256, GEMM_SMEM>>>(sBhi, sBlo, GThi, GTlo, cbuf,
                                               dst, dup, nh, nl);
    }
}

// round 5
// speedup vs baseline: 1.9141x; 1.0308x over previous
#include <cuda_runtime.h>
#include <cuda_bf16.h>
#include <stdint.h>

// ---------------------------------------------------------------------------
// SORNet via affine recurrence  s_k = s_{k-1} @ G + c, GEMMs on legacy tensor
// cores (mma.sync m16n8k16 bf16 -> f32) with bf16x3 split operands.
// This round: 512-thread CTA (4 warps/SMSP), warp tile 32x32, single sync per
// k-chunk, term-major MMA ordering.
// ---------------------------------------------------------------------------

#define ND 1024
#define BSD 2048

// fp32 scratch
__device__ __align__(1024) float g_invM[ND * ND];
__device__ __align__(1024) float g_yMF[BSD * ND];
__device__ __align__(1024) float g_c[BSD * ND];
__device__ __align__(1024) float g_G[ND * ND];
__device__ float g_d[ND];

// bf16 split operands
__device__ __align__(1024) __nv_bfloat16 g_Hhi[ND * ND];
__device__ __align__(1024) __nv_bfloat16 g_Hlo[ND * ND];
__device__ __align__(1024) __nv_bfloat16 g_yhi[BSD * ND];
__device__ __align__(1024) __nv_bfloat16 g_ylo[BSD * ND];
__device__ __align__(1024) __nv_bfloat16 g_yMFhi[BSD * ND];
__device__ __align__(1024) __nv_bfloat16 g_yMFlo[BSD * ND];
__device__ __align__(1024) __nv_bfloat16 g_iMThi[ND * ND];
__device__ __align__(1024) __nv_bfloat16 g_iMTlo[ND * ND];
__device__ __align__(1024) __nv_bfloat16 g_Thi[ND * ND];
__device__ __align__(1024) __nv_bfloat16 g_Tlo[ND * ND];
__device__ __align__(1024) __nv_bfloat16 g_GThi[ND * ND];
__device__ __align__(1024) __nv_bfloat16 g_GTlo[ND * ND];
__device__ __align__(1024) __nv_bfloat16 g_sAhi[BSD * ND];
__device__ __align__(1024) __nv_bfloat16 g_sAlo[BSD * ND];
__device__ __align__(1024) __nv_bfloat16 g_sBhi[BSD * ND];
__device__ __align__(1024) __nv_bfloat16 g_sBlo[BSD * ND];

// ---------------------------------------------------------------------------
__device__ __forceinline__ uint32_t smem_u32(const void* p) {
    uint32_t a;
    asm("{ .reg .u64 t; cvta.to.shared.u64 t, %1; cvt.u32.u64 %0, t; }"
        : "=r"(a) : "l"(p));
    return a;
}

__device__ __forceinline__ void ldm_x4(uint32_t (&r)[4], uint32_t addr) {
    asm volatile(
        "ldmatrix.sync.aligned.m8n8.x4.shared.b16 {%0,%1,%2,%3}, [%4];"
        : "=r"(r[0]), "=r"(r[1]), "=r"(r[2]), "=r"(r[3]) : "r"(addr));
}

__device__ __forceinline__ void mma16816(float* c, const uint32_t* a,
                                         const uint32_t* b) {
    asm volatile(
        "mma.sync.aligned.m16n8k16.row.col.f32.bf16.bf16.f32 "
        "{%0,%1,%2,%3}, {%4,%5,%6,%7}, {%8,%9}, {%0,%1,%2,%3};"
        : "+f"(c[0]), "+f"(c[1]), "+f"(c[2]), "+f"(c[3])
        : "r"(a[0]), "r"(a[1]), "r"(a[2]), "r"(a[3]), "r"(b[0]), "r"(b[1]));
}

__device__ __forceinline__ void cp16(uint32_t sdst, const void* gsrc) {
    asm volatile("cp.async.cg.shared.global [%0], [%1], 16;" ::"r"(sdst),
                 "l"(gsrc));
}
#define CP_COMMIT() asm volatile("cp.async.commit_group;" ::: "memory")
#define CP_WAIT1() asm volatile("cp.async.wait_group 1;" ::: "memory")

__device__ __forceinline__ void split2(float x, __nv_bfloat16& h,
                                       __nv_bfloat16& l) {
    h = __float2bfloat16(x);
    l = __float2bfloat16(x - __bfloat162float(h));
}

// ---------------------------------------------------------------------------
// small kernels
// ---------------------------------------------------------------------------
__global__ void prep_split_kernel(const float* __restrict__ A,
                                  const float* __restrict__ pw,
                                  __nv_bfloat16* __restrict__ Thi,
                                  __nv_bfloat16* __restrict__ Tlo,
                                  float* __restrict__ dvec) {
    int idx = blockIdx.x * blockDim.x + threadIdx.x;
    if (idx >= ND * ND) return;
    int i = idx >> 10, k = idx & (ND - 1);
    float w = *pw;
    float a = A[idx];
    float t = 0.0f;
    if (i == k) {
        t = (w - 1.0f) * a;
        dvec[i] = a;
    } else if (i < k) {
        t = -a;
    }
    __nv_bfloat16 h, l;
    split2(t, h, l);
    Thi[idx] = h;
    Tlo[idx] = l;
}

__global__ void split_ew_kernel(const float* __restrict__ in,
                                __nv_bfloat16* __restrict__ hi,
                                __nv_bfloat16* __restrict__ lo, int total) {
    int i = blockIdx.x * blockDim.x + threadIdx.x;
    if (i >= total) return;
    __nv_bfloat16 h, l;
    split2(in[i], h, l);
    hi[i] = h;
    lo[i] = l;
}

__global__ void tsplit_kernel(const float* __restrict__ in,
                              __nv_bfloat16* __restrict__ oh,
                              __nv_bfloat16* __restrict__ ol) {
    __shared__ float t[32][33];
    int bx = blockIdx.x * 32, by = blockIdx.y * 32;
    for (int r = threadIdx.y; r < 32; r += 8)
        t[r][threadIdx.x] = in[(size_t)(by + r) * ND + bx + threadIdx.x];
    __syncthreads();
    for (int r = threadIdx.y; r < 32; r += 8) {
        float v = t[threadIdx.x][r];
        __nv_bfloat16 h, l;
        split2(v, h, l);
        size_t o = (size_t)(bx + r) * ND + by + threadIdx.x;
        oh[o] = h;
        ol[o] = l;
    }
}

__global__ void s0split_kernel(const float* __restrict__ yMF,
                               const float* __restrict__ dvec,
                               __nv_bfloat16* __restrict__ hi,
                               __nv_bfloat16* __restrict__ lo,
                               float* __restrict__ traj0, int total) {
    int i = blockIdx.x * blockDim.x + threadIdx.x;
    if (i >= total) return;
    float v = yMF[i] / dvec[i & (ND - 1)];
    __nv_bfloat16 h, l;
    split2(v, h, l);
    hi[i] = h;
    lo[i] = l;
    traj0[i] = 0.0f;
}

__global__ __launch_bounds__(256) void trinv_kernel(const float* __restrict__ A,
                                                    const float* __restrict__ pw,
                                                    float* __restrict__ X) {
    __shared__ float xs_all[8][ND];
    int lane = threadIdx.x & 31;
    int warpInBlk = threadIdx.x >> 5;
    int j = blockIdx.x * 8 + warpInBlk;
    if (j >= ND) return;
    float* xs = xs_all[warpInBlk];
    float w = *pw;
    for (int i = lane; i < j; i += 32) X[(size_t)i * ND + j] = 0.0f;
    float xjj = 1.0f / (w * A[(size_t)j * ND + j]);
    if (lane == 0) {
        xs[j] = xjj;
        X[(size_t)j * ND + j] = xjj;
    }
    __syncwarp();
    for (int i = j + 1; i < ND; i++) {
        const float* Arow = A + (size_t)i * ND;
        float s = 0.0f;
        for (int k = j + lane; k < i; k += 32) s += Arow[k] * xs[k];
#pragma unroll
        for (int o = 16; o > 0; o >>= 1) s += __shfl_xor_sync(0xFFFFFFFFu, s, o);
        float xi = -s / (w * Arow[i]);
        if (lane == 0) {
            xs[i] = xi;
            X[(size_t)i * ND + j] = xi;
        }
        __syncwarp();
    }
}

// ---------------------------------------------------------------------------
// split-GEMM on mma.sync: D[M,1024] = Ahi@Bhi^T + Ahi@Blo^T + Alo@Bhi^T (+C)
// CTA 128x128, BK=32, 3-stage cp.async, 16 warps (4x4 grid), warp tile 32x32,
// one __syncthreads per chunk. Epilogue: +Cadd, fp32 out (+dup), opt splits.
// ---------------------------------------------------------------------------
#define RS 40               // padded row stride in bf16 (80 B)
#define TILE_E (128 * RS)   // elems per tile
#define STG_E (4 * TILE_E)  // Ahi, Alo, Bhi, Blo
#define NSTAGE 3
#define GEMM_SMEM (NSTAGE * STG_E * 2)
#define NKCH 32  // 1024 / 32

__global__ __launch_bounds__(512, 1) void mma_gemm(
    const __nv_bfloat16* __restrict__ Ahi, const __nv_bfloat16* __restrict__ Alo,
    const __nv_bfloat16* __restrict__ Bhi, const __nv_bfloat16* __restrict__ Blo,
    const float* __restrict__ Cadd, float* __restrict__ outD,
    float* __restrict__ outDup, __nv_bfloat16* __restrict__ nHi,
    __nv_bfloat16* __restrict__ nLo) {
    extern __shared__ __align__(128) __nv_bfloat16 smg[];
    const uint32_t sbase = smem_u32(smg);
    const int tid = threadIdx.x;
    const int lane = tid & 31, wid = tid >> 5;
    const int warpM = wid >> 2, warpN = wid & 3;  // 4 x 4 warp grid
    const int bm0 = blockIdx.y * 128, bn0 = blockIdx.x * 128;

    float acc[2][4][4];
#pragma unroll
    for (int a = 0; a < 2; a++)
#pragma unroll
        for (int b = 0; b < 4; b++)
#pragma unroll
            for (int e = 0; e < 4; e++) acc[a][b][e] = 0.0f;

    // cp.async per-thread coords: 512 threads cover one 128x32 tile exactly
    const int c0r = tid >> 2;       // 0..127
    const int c0k = (tid & 3) * 8;  // bf16 elems

    // ldmatrix per-lane offsets (element units within a tile)
    const int aRow = warpM * 32 + (lane & 15);
    const int aOffB = aRow * RS + ((lane >> 4) << 3);
    const int nB = warpN * 32 + ((lane >> 4) << 3) + (lane & 7);
    const int bOffB = nB * RS + (((lane >> 3) & 1) << 3);

#define LOAD_STAGE(slot, kc0)                                    \
    do {                                                         \
        uint32_t sa = sbase + (uint32_t)(slot) * (STG_E * 2);    \
        int kk = (kc0);                                          \
        uint32_t so = (uint32_t)(c0r * RS + c0k) * 2;            \
        size_t go = (size_t)c0r * ND + kk + c0k;                 \
        cp16(sa + so, Ahi + (size_t)bm0 * ND + go);              \
        cp16(sa + TILE_E * 2 + so, Alo + (size_t)bm0 * ND + go); \
        cp16(sa + 2 * TILE_E * 2 + so, Bhi + (size_t)bn0 * ND + go); \
        cp16(sa + 3 * TILE_E * 2 + so, Blo + (size_t)bn0 * ND + go); \
    } while (0)

    LOAD_STAGE(0, 0);
    CP_COMMIT();
    LOAD_STAGE(1, 32);
    CP_COMMIT();

    for (int ck = 0; ck < NKCH; ck++) {
        CP_WAIT1();
        __syncthreads();
        if (ck + 2 < NKCH) LOAD_STAGE((ck + 2) % NSTAGE, (ck + 2) * 32);
        CP_COMMIT();

        uint32_t sa = sbase + (uint32_t)(ck % NSTAGE) * (STG_E * 2);
#pragma unroll
        for (int ks = 0; ks < 2; ks++) {
            uint32_t ah[2][4], al[2][4];
            uint32_t bh[4][2], bl[4][2];
#pragma unroll
            for (int im = 0; im < 2; im++) {
                uint32_t off = (uint32_t)(aOffB + im * 16 * RS + ks * 16) * 2;
                ldm_x4(ah[im], sa + off);
                ldm_x4(al[im], sa + (uint32_t)(TILE_E * 2) + off);
            }
#pragma unroll
            for (int ig = 0; ig < 2; ig++) {
                uint32_t off = (uint32_t)(bOffB + ig * 16 * RS + ks * 16) * 2;
                uint32_t t[4];
                ldm_x4(t, sa + (uint32_t)(2 * TILE_E * 2) + off);
                bh[2 * ig][0] = t[0]; bh[2 * ig][1] = t[1];
                bh[2 * ig + 1][0] = t[2]; bh[2 * ig + 1][1] = t[3];
                ldm_x4(t, sa + (uint32_t)(3 * TILE_E * 2) + off);
                bl[2 * ig][0] = t[0]; bl[2 * ig][1] = t[1];
                bl[2 * ig + 1][0] = t[2]; bl[2 * ig + 1][1] = t[3];
            }
            // term-major ordering: 8 independent MMAs between dependent ones
#pragma unroll
            for (int im = 0; im < 2; im++)
#pragma unroll
                for (int in = 0; in < 4; in++) mma16816(acc[im][in], ah[im], bh[in]);
#pragma unroll
            for (int im = 0; im < 2; im++)
#pragma unroll
                for (int in = 0; in < 4; in++) mma16816(acc[im][in], ah[im], bl[in]);
#pragma unroll
            for (int im = 0; im < 2; im++)
#pragma unroll
                for (int in = 0; in < 4; in++) mma16816(acc[im][in], al[im], bh[in]);
        }
    }

    // ---- epilogue ----
    const int gr = lane >> 2;
    const int gc = (lane & 3) * 2;
#pragma unroll
    for (int im = 0; im < 2; im++) {
#pragma unroll
        for (int in = 0; in < 4; in++) {
            int row0 = bm0 + warpM * 32 + im * 16 + gr;
            int col = bn0 + warpN * 32 + in * 8 + gc;
#pragma unroll
            for (int hh = 0; hh < 2; hh++) {
                size_t off = (size_t)(row0 + hh * 8) * ND + col;
                float x = acc[im][in][hh * 2 + 0];
                float y = acc[im][in][hh * 2 + 1];
                if (Cadd) {
                    float2 cv = *reinterpret_cast<const float2*>(Cadd + off);
                    x += cv.x;
                    y += cv.y;
                }
                *reinterpret_cast<float2*>(outD + off) = make_float2(x, y);
                if (outDup)
                    *reinterpret_cast<float2*>(outDup + off) = make_float2(x, y);
                if (nHi) {
                    __nv_bfloat16 hx, lx, hy, ly;
                    split2(x, hx, lx);
                    split2(y, hy, ly);
                    *reinterpret_cast<__nv_bfloat162*>(nHi + off) =
                        __halves2bfloat162(hx, hy);
                    *reinterpret_cast<__nv_bfloat162*>(nLo + off) =
                        __halves2bfloat162(lx, ly);
                }
            }
        }
    }
#undef LOAD_STAGE
}

// ---------------------------------------------------------------------------
extern "C" void kernel_launch(void* const* d_in, const int* in_sizes, int n_in,
                              void* d_out, int out_size) {
    const float* A = (const float*)d_in[0];
    const float* H = (const float*)d_in[1];
    const float* y = (const float*)d_in[2];
    const float* pw = (const float*)d_in[3];

    int n = ND;
    int bs = in_sizes[2] / n;
    int itr = out_size / (bs * n) - 2;

    float *invM, *yMF, *cbuf, *Gbuf, *dvec;
    cudaGetSymbolAddress((void**)&invM, g_invM);
    cudaGetSymbolAddress((void**)&yMF, g_yMF);
    cudaGetSymbolAddress((void**)&cbuf, g_c);
    cudaGetSymbolAddress((void**)&Gbuf, g_G);
    cudaGetSymbolAddress((void**)&dvec, g_d);
    __nv_bfloat16 *Hhi, *Hlo, *yhi, *ylo, *yMFhi, *yMFlo, *iMThi, *iMTlo;
    __nv_bfloat16 *Thi, *Tlo, *GThi, *GTlo, *sAhi, *sAlo, *sBhi, *sBlo;
    cudaGetSymbolAddress((void**)&Hhi, g_Hhi);
    cudaGetSymbolAddress((void**)&Hlo, g_Hlo);
    cudaGetSymbolAddress((void**)&yhi, g_yhi);
    cudaGetSymbolAddress((void**)&ylo, g_ylo);
    cudaGetSymbolAddress((void**)&yMFhi, g_yMFhi);
    cudaGetSymbolAddress((void**)&yMFlo, g_yMFlo);
    cudaGetSymbolAddress((void**)&iMThi, g_iMThi);
    cudaGetSymbolAddress((void**)&iMTlo, g_iMTlo);
    cudaGetSymbolAddress((void**)&Thi, g_Thi);
    cudaGetSymbolAddress((void**)&Tlo, g_Tlo);
    cudaGetSymbolAddress((void**)&GThi, g_GThi);
    cudaGetSymbolAddress((void**)&GTlo, g_GTlo);
    cudaGetSymbolAddress((void**)&sAhi, g_sAhi);
    cudaGetSymbolAddress((void**)&sAlo, g_sAlo);
    cudaGetSymbolAddress((void**)&sBhi, g_sBhi);
    cudaGetSymbolAddress((void**)&sBlo, g_sBlo);

    cudaFuncSetAttribute(mma_gemm, cudaFuncAttributeMaxDynamicSharedMemorySize,
                         GEMM_SMEM);

    float* out = (float*)d_out;
    float* traj = out + (size_t)bs * n;

    // setup
    prep_split_kernel<<<(n * n + 255) / 256, 256>>>(A, pw, Thi, Tlo, dvec);
    trinv_kernel<<<(n + 7) / 8, 256>>>(A, pw, invM);
    split_ew_kernel<<<(bs * n + 255) / 256, 256>>>(y, yhi, ylo, bs * n);
    split_ew_kernel<<<(n * n + 255) / 256, 256>>>(H, Hhi, Hlo, n * n);
    tsplit_kernel<<<dim3(32, 32), dim3(32, 8)>>>(invM, iMThi, iMTlo);

    dim3 gBig(n / 128, bs / 128);
    dim3 gSq(n / 128, n / 128);

    // yMF = y @ H^T  (emit yMF splits)
    mma_gemm<<<gBig, 512, GEMM_SMEM>>>(yhi, ylo, Hhi, Hlo, nullptr, yMF,
                                       nullptr, yMFhi, yMFlo);
    // s0 splits + traj[0] = 0
    s0split_kernel<<<(bs * n + 255) / 256, 256>>>(yMF, dvec, sAhi, sAlo, traj,
                                                  bs * n);
    // c = yMF @ invM
    mma_gemm<<<gBig, 512, GEMM_SMEM>>>(yMFhi, yMFlo, iMThi, iMTlo, nullptr,
                                       cbuf, nullptr, nullptr, nullptr);
    // G^T = invM^T @ T^T  (emit GT splits)
    mma_gemm<<<gSq, 512, GEMM_SMEM>>>(iMThi, iMTlo, Thi, Tlo, nullptr, Gbuf,
                                      nullptr, GThi, GTlo);

    // loop: s_k = s_{k-1} @ G + c
    for (int k = 1; k <= itr; k++) {
        float* dst = traj + (size_t)k * bs * n;
        float* dup = (k == itr) ? out : nullptr;
        bool aIsA = (k & 1);
        __nv_bfloat16* nh = (k == itr) ? nullptr : (aIsA ? sBhi : sAhi);
        __nv_bfloat16* nl = (k == itr) ? nullptr : (aIsA ? sBlo : sAlo);
        if (aIsA)
            mma_gemm<<<gBig, 512, GEMM_SMEM>>>(sAhi, sAlo, GThi, GTlo, cbuf,
                                               dst, dup, nh, nl);
        else
            mma_gemm<<<gBig, 512, GEMM_SMEM>>>(sBhi, sBlo, GThi, GTlo, cbuf,
                                               dst, dup, nh, nl);
    }
}

// round 6
// speedup vs baseline: 2.1896x; 1.1439x over previous
#include <cuda_runtime.h>
#include <cuda_fp16.h>
#include <stdint.h>

// ---------------------------------------------------------------------------
// SORNet via affine recurrence  s_k = s_{k-1} @ G + c.
// GEMMs on mma.sync m16n8k16 fp16->f32 with fp16x2 A-split (Ahi + Alo) and
// fp16-rounded B:  D = Ahi@Bh + Alo@Bh  (dropped A@Blo ~ 2^-12 rel).
//   invM = inv(w*D + L); T = (w-1)*D - U; yMF = y@H^T; c = yMF@invM;
//   G^T = invM^T @ T^T; loop s_k = s_{k-1}@G + c.
// Output: [s_final | traj(itr+1 slabs)], traj[0]=0.
// ---------------------------------------------------------------------------

#define ND 1024
#define BSD 2048

// fp32 scratch
__device__ __align__(1024) float g_invM[ND * ND];
__device__ __align__(1024) float g_yMF[BSD * ND];
__device__ __align__(1024) float g_c[BSD * ND];
__device__ __align__(1024) float g_G[ND * ND];
__device__ float g_d[ND];

// fp16 operands
__device__ __align__(1024) __half g_Hh[ND * ND];      // B of yMF gemm
__device__ __align__(1024) __half g_yhi[BSD * ND];    // A of yMF gemm
__device__ __align__(1024) __half g_ylo[BSD * ND];
__device__ __align__(1024) __half g_MFhi[BSD * ND];   // A of c gemm
__device__ __align__(1024) __half g_MFlo[BSD * ND];
__device__ __align__(1024) __half g_iMThi[ND * ND];   // A of GT gemm, B of c gemm
__device__ __align__(1024) __half g_iMTlo[ND * ND];
__device__ __align__(1024) __half g_Th[ND * ND];      // B of GT gemm
__device__ __align__(1024) __half g_GThi[ND * ND];    // B of loop gemms
__device__ __align__(1024) __half g_GTlo[ND * ND];    // (emitted, unused)
__device__ __align__(1024) __half g_sAhi[BSD * ND];
__device__ __align__(1024) __half g_sAlo[BSD * ND];
__device__ __align__(1024) __half g_sBhi[BSD * ND];
__device__ __align__(1024) __half g_sBlo[BSD * ND];

// ---------------------------------------------------------------------------
__device__ __forceinline__ uint32_t smem_u32(const void* p) {
    uint32_t a;
    asm("{ .reg .u64 t; cvta.to.shared.u64 t, %1; cvt.u32.u64 %0, t; }"
        : "=r"(a) : "l"(p));
    return a;
}

__device__ __forceinline__ void ldm_x4(uint32_t (&r)[4], uint32_t addr) {
    asm volatile(
        "ldmatrix.sync.aligned.m8n8.x4.shared.b16 {%0,%1,%2,%3}, [%4];"
        : "=r"(r[0]), "=r"(r[1]), "=r"(r[2]), "=r"(r[3]) : "r"(addr));
}

__device__ __forceinline__ void mma16816(float* c, const uint32_t* a,
                                         const uint32_t* b) {
    asm volatile(
        "mma.sync.aligned.m16n8k16.row.col.f32.f16.f16.f32 "
        "{%0,%1,%2,%3}, {%4,%5,%6,%7}, {%8,%9}, {%0,%1,%2,%3};"
        : "+f"(c[0]), "+f"(c[1]), "+f"(c[2]), "+f"(c[3])
        : "r"(a[0]), "r"(a[1]), "r"(a[2]), "r"(a[3]), "r"(b[0]), "r"(b[1]));
}

__device__ __forceinline__ void cp16(uint32_t sdst, const void* gsrc) {
    asm volatile("cp.async.cg.shared.global [%0], [%1], 16;" ::"r"(sdst),
                 "l"(gsrc));
}
#define CP_COMMIT() asm volatile("cp.async.commit_group;" ::: "memory")
#define CP_WAIT1() asm volatile("cp.async.wait_group 1;" ::: "memory")

__device__ __forceinline__ void split2h(float x, __half& h, __half& l) {
    h = __float2half(x);
    l = __float2half(x - __half2float(h));
}

// ---------------------------------------------------------------------------
// small kernels
// ---------------------------------------------------------------------------
__global__ void prep_kernel(const float* __restrict__ A,
                            const float* __restrict__ pw,
                            __half* __restrict__ Th, float* __restrict__ dvec) {
    int idx = blockIdx.x * blockDim.x + threadIdx.x;
    if (idx >= ND * ND) return;
    int i = idx >> 10, k = idx & (ND - 1);
    float w = *pw;
    float a = A[idx];
    float t = 0.0f;
    if (i == k) {
        t = (w - 1.0f) * a;
        dvec[i] = a;
    } else if (i < k) {
        t = -a;
    }
    Th[idx] = __float2half(t);
}

__global__ void split_ew_kernel(const float* __restrict__ in,
                                __half* __restrict__ hi,
                                __half* __restrict__ lo, int total) {
    int i = blockIdx.x * blockDim.x + threadIdx.x;
    if (i >= total) return;
    __half h, l;
    split2h(in[i], h, l);
    hi[i] = h;
    lo[i] = l;
}

__global__ void round_ew_kernel(const float* __restrict__ in,
                                __half* __restrict__ hi, int total) {
    int i = blockIdx.x * blockDim.x + threadIdx.x;
    if (i >= total) return;
    hi[i] = __float2half(in[i]);
}

// transpose + split: out[n][m] = split(in[m][n]), ND x ND
__global__ void tsplit_kernel(const float* __restrict__ in,
                              __half* __restrict__ oh,
                              __half* __restrict__ ol) {
    __shared__ float t[32][33];
    int bx = blockIdx.x * 32, by = blockIdx.y * 32;
    for (int r = threadIdx.y; r < 32; r += 8)
        t[r][threadIdx.x] = in[(size_t)(by + r) * ND + bx + threadIdx.x];
    __syncthreads();
    for (int r = threadIdx.y; r < 32; r += 8) {
        float v = t[threadIdx.x][r];
        __half h, l;
        split2h(v, h, l);
        size_t o = (size_t)(bx + r) * ND + by + threadIdx.x;
        oh[o] = h;
        ol[o] = l;
    }
}

__global__ void s0split_kernel(const float* __restrict__ yMF,
                               const float* __restrict__ dvec,
                               __half* __restrict__ hi,
                               __half* __restrict__ lo,
                               float* __restrict__ traj0, int total) {
    int i = blockIdx.x * blockDim.x + threadIdx.x;
    if (i >= total) return;
    float v = yMF[i] / dvec[i & (ND - 1)];
    __half h, l;
    split2h(v, h, l);
    hi[i] = h;
    lo[i] = l;
    traj0[i] = 0.0f;
}

__global__ __launch_bounds__(256) void trinv_kernel(const float* __restrict__ A,
                                                    const float* __restrict__ pw,
                                                    float* __restrict__ X) {
    __shared__ float xs_all[8][ND];
    int lane = threadIdx.x & 31;
    int warpInBlk = threadIdx.x >> 5;
    int j = blockIdx.x * 8 + warpInBlk;
    if (j >= ND) return;
    float* xs = xs_all[warpInBlk];
    float w = *pw;
    for (int i = lane; i < j; i += 32) X[(size_t)i * ND + j] = 0.0f;
    float xjj = 1.0f / (w * A[(size_t)j * ND + j]);
    if (lane == 0) {
        xs[j] = xjj;
        X[(size_t)j * ND + j] = xjj;
    }
    __syncwarp();
    for (int i = j + 1; i < ND; i++) {
        const float* Arow = A + (size_t)i * ND;
        float s = 0.0f;
        for (int k = j + lane; k < i; k += 32) s += Arow[k] * xs[k];
#pragma unroll
        for (int o = 16; o > 0; o >>= 1) s += __shfl_xor_sync(0xFFFFFFFFu, s, o);
        float xi = -s / (w * Arow[i]);
        if (lane == 0) {
            xs[i] = xi;
            X[(size_t)i * ND + j] = xi;
        }
        __syncwarp();
    }
}

// ---------------------------------------------------------------------------
// split-GEMM on mma.sync: D[M,1024] = Ahi@Bh^T + Alo@Bh^T (+Cadd)
// A arrays: [M][1024] fp16 row-major; B array: [1024][1024] fp16 (B^T layout).
// CTA 128x128, BK=32, 3-stage cp.async, 16 warps (4x4), warp tile 32x32.
// Epilogue: +Cadd, fp32 out (+dup), optional fp16 hi/lo splits of result.
// ---------------------------------------------------------------------------
#define RS 40               // padded row stride in fp16 (80 B)
#define TILE_E (128 * RS)   // elems per tile
#define STG_E (3 * TILE_E)  // Ahi, Alo, Bh
#define NSTAGE 3
#define GEMM_SMEM (NSTAGE * STG_E * 2)
#define NKCH 32  // 1024 / 32

__global__ __launch_bounds__(512, 1) void mma_gemm(
    const __half* __restrict__ Ahi, const __half* __restrict__ Alo,
    const __half* __restrict__ Bh, const float* __restrict__ Cadd,
    float* __restrict__ outD, float* __restrict__ outDup,
    __half* __restrict__ nHi, __half* __restrict__ nLo) {
    extern __shared__ __align__(128) __half smg[];
    const uint32_t sbase = smem_u32(smg);
    const int tid = threadIdx.x;
    const int lane = tid & 31, wid = tid >> 5;
    const int warpM = wid >> 2, warpN = wid & 3;  // 4 x 4 warp grid
    const int bm0 = blockIdx.y * 128, bn0 = blockIdx.x * 128;

    float acc[2][4][4];
#pragma unroll
    for (int a = 0; a < 2; a++)
#pragma unroll
        for (int b = 0; b < 4; b++)
#pragma unroll
            for (int e = 0; e < 4; e++) acc[a][b][e] = 0.0f;

    // cp.async per-thread coords: 512 threads cover one 128x32 tile exactly
    const int c0r = tid >> 2;       // 0..127
    const int c0k = (tid & 3) * 8;  // fp16 elems

    // ldmatrix per-lane offsets (element units within a tile)
    const int aRow = warpM * 32 + (lane & 15);
    const int aOffB = aRow * RS + ((lane >> 4) << 3);
    const int nB = warpN * 32 + ((lane >> 4) << 3) + (lane & 7);
    const int bOffB = nB * RS + (((lane >> 3) & 1) << 3);

#define LOAD_STAGE(slot, kc0)                                        \
    do {                                                             \
        uint32_t sa = sbase + (uint32_t)(slot) * (STG_E * 2);        \
        int kk = (kc0);                                              \
        uint32_t so = (uint32_t)(c0r * RS + c0k) * 2;                \
        size_t go = (size_t)c0r * ND + kk + c0k;                     \
        cp16(sa + so, Ahi + (size_t)bm0 * ND + go);                  \
        cp16(sa + TILE_E * 2 + so, Alo + (size_t)bm0 * ND + go);     \
        cp16(sa + 2 * TILE_E * 2 + so, Bh + (size_t)bn0 * ND + go);  \
    } while (0)

    LOAD_STAGE(0, 0);
    CP_COMMIT();
    LOAD_STAGE(1, 32);
    CP_COMMIT();

    for (int ck = 0; ck < NKCH; ck++) {
        CP_WAIT1();
        __syncthreads();
        if (ck + 2 < NKCH) LOAD_STAGE((ck + 2) % NSTAGE, (ck + 2) * 32);
        CP_COMMIT();

        uint32_t sa = sbase + (uint32_t)(ck % NSTAGE) * (STG_E * 2);
#pragma unroll
        for (int ks = 0; ks < 2; ks++) {
            uint32_t ah[2][4], al[2][4];
            uint32_t bh[4][2];
#pragma unroll
            for (int im = 0; im < 2; im++) {
                uint32_t off = (uint32_t)(aOffB + im * 16 * RS + ks * 16) * 2;
                ldm_x4(ah[im], sa + off);
                ldm_x4(al[im], sa + (uint32_t)(TILE_E * 2) + off);
            }
#pragma unroll
            for (int ig = 0; ig < 2; ig++) {
                uint32_t off = (uint32_t)(bOffB + ig * 16 * RS + ks * 16) * 2;
                uint32_t t[4];
                ldm_x4(t, sa + (uint32_t)(2 * TILE_E * 2) + off);
                bh[2 * ig][0] = t[0]; bh[2 * ig][1] = t[1];
                bh[2 * ig + 1][0] = t[2]; bh[2 * ig + 1][1] = t[3];
            }
            // term-major: 8 independent MMAs between accumulator reuses
#pragma unroll
            for (int im = 0; im < 2; im++)
#pragma unroll
                for (int in = 0; in < 4; in++) mma16816(acc[im][in], ah[im], bh[in]);
#pragma unroll
            for (int im = 0; im < 2; im++)
#pragma unroll
                for (int in = 0; in < 4; in++) mma16816(acc[im][in], al[im], bh[in]);
        }
    }

    // ---- epilogue ----
    const int gr = lane >> 2;
    const int gc = (lane & 3) * 2;
#pragma unroll
    for (int im = 0; im < 2; im++) {
#pragma unroll
        for (int in = 0; in < 4; in++) {
            int row0 = bm0 + warpM * 32 + im * 16 + gr;
            int col = bn0 + warpN * 32 + in * 8 + gc;
#pragma unroll
            for (int hh = 0; hh < 2; hh++) {
                size_t off = (size_t)(row0 + hh * 8) * ND + col;
                float x = acc[im][in][hh * 2 + 0];
                float y = acc[im][in][hh * 2 + 1];
                if (Cadd) {
                    float2 cv = *reinterpret_cast<const float2*>(Cadd + off);
                    x += cv.x;
                    y += cv.y;
                }
                *reinterpret_cast<float2*>(outD + off) = make_float2(x, y);
                if (outDup)
                    *reinterpret_cast<float2*>(outDup + off) = make_float2(x, y);
                if (nHi) {
                    __half hx, lx, hy, ly;
                    split2h(x, hx, lx);
                    split2h(y, hy, ly);
                    *reinterpret_cast<__half2*>(nHi + off) =
                        __halves2half2(hx, hy);
                    *reinterpret_cast<__half2*>(nLo + off) =
                        __halves2half2(lx, ly);
                }
            }
        }
    }
#undef LOAD_STAGE
}

// ---------------------------------------------------------------------------
extern "C" void kernel_launch(void* const* d_in, const int* in_sizes, int n_in,
                              void* d_out, int out_size) {
    const float* A = (const float*)d_in[0];
    const float* H = (const float*)d_in[1];
    const float* y = (const float*)d_in[2];
    const float* pw = (const float*)d_in[3];

    int n = ND;
    int bs = in_sizes[2] / n;
    int itr = out_size / (bs * n) - 2;

    float *invM, *yMF, *cbuf, *Gbuf, *dvec;
    cudaGetSymbolAddress((void**)&invM, g_invM);
    cudaGetSymbolAddress((void**)&yMF, g_yMF);
    cudaGetSymbolAddress((void**)&cbuf, g_c);
    cudaGetSymbolAddress((void**)&Gbuf, g_G);
    cudaGetSymbolAddress((void**)&dvec, g_d);
    __half *Hh, *yhi, *ylo, *MFhi, *MFlo, *iMThi, *iMTlo, *Th;
    __half *GThi, *GTlo, *sAhi, *sAlo, *sBhi, *sBlo;
    cudaGetSymbolAddress((void**)&Hh, g_Hh);
    cudaGetSymbolAddress((void**)&yhi, g_yhi);
    cudaGetSymbolAddress((void**)&ylo, g_ylo);
    cudaGetSymbolAddress((void**)&MFhi, g_MFhi);
    cudaGetSymbolAddress((void**)&MFlo, g_MFlo);
    cudaGetSymbolAddress((void**)&iMThi, g_iMThi);
    cudaGetSymbolAddress((void**)&iMTlo, g_iMTlo);
    cudaGetSymbolAddress((void**)&Th, g_Th);
    cudaGetSymbolAddress((void**)&GThi, g_GThi);
    cudaGetSymbolAddress((void**)&GTlo, g_GTlo);
    cudaGetSymbolAddress((void**)&sAhi, g_sAhi);
    cudaGetSymbolAddress((void**)&sAlo, g_sAlo);
    cudaGetSymbolAddress((void**)&sBhi, g_sBhi);
    cudaGetSymbolAddress((void**)&sBlo, g_sBlo);

    cudaFuncSetAttribute(mma_gemm, cudaFuncAttributeMaxDynamicSharedMemorySize,
                         GEMM_SMEM);

    float* out = (float*)d_out;
    float* traj = out + (size_t)bs * n;

    // setup
    prep_kernel<<<(n * n + 255) / 256, 256>>>(A, pw, Th, dvec);
    trinv_kernel<<<(n + 7) / 8, 256>>>(A, pw, invM);
    split_ew_kernel<<<(bs * n + 255) / 256, 256>>>(y, yhi, ylo, bs * n);
    round_ew_kernel<<<(n * n + 255) / 256, 256>>>(H, Hh, n * n);
    tsplit_kernel<<<dim3(32, 32), dim3(32, 8)>>>(invM, iMThi, iMTlo);

    dim3 gBig(n / 128, bs / 128);
    dim3 gSq(n / 128, n / 128);

    // yMF = y @ H^T  (emit yMF splits)
    mma_gemm<<<gBig, 512, GEMM_SMEM>>>(yhi, ylo, Hh, nullptr, yMF, nullptr,
                                       MFhi, MFlo);
    // s0 splits + traj[0] = 0
    s0split_kernel<<<(bs * n + 255) / 256, 256>>>(yMF, dvec, sAhi, sAlo, traj,
                                                  bs * n);
    // c = yMF @ invM   (B = invM^T hi)
    mma_gemm<<<gBig, 512, GEMM_SMEM>>>(MFhi, MFlo, iMThi, nullptr, cbuf,
                                       nullptr, nullptr, nullptr);
    // G^T = invM^T @ T^T  (B = T hi; emit GT splits)
    mma_gemm<<<gSq, 512, GEMM_SMEM>>>(iMThi, iMTlo, Th, nullptr, Gbuf, nullptr,
                                      GThi, GTlo);

    // loop: s_k = s_{k-1} @ G + c
    for (int k = 1; k <= itr; k++) {
        float* dst = traj + (size_t)k * bs * n;
        float* dup = (k == itr) ? out : nullptr;
        bool aIsA = (k & 1);
        __half* nh = (k == itr) ? nullptr : (aIsA ? sBhi : sAhi);
        __half* nl = (k == itr) ? nullptr : (aIsA ? sBlo : sAlo);
        if (aIsA)
            mma_gemm<<<gBig, 512, GEMM_SMEM>>>(sAhi, sAlo, GThi, cbuf, dst,
                                               dup, nh, nl);
        else
            mma_gemm<<<gBig, 512, GEMM_SMEM>>>(sBhi, sBlo, GThi, cbuf, dst,
                                               dup, nh, nl);
    }
}